// round 9
// baseline (speedup 1.0000x reference)
#include <cuda_runtime.h>
#include <cuda_fp16.h>

#define SS   1024
#define BB   8
#define NH   8
#define BH   (BB * NH)          // 64

// Scratch: attention out in ROW-FEATURE layout [b*1024+s][h*8+d]  (2 MB)
__device__ float g_ao[BB * SS * 64];

// smem: kh[1024][8] half (16KB), vt[8][1032] half (16.5KB)
#define SM_KH 0
#define SM_VT 16384
#define VT_STRIDE 1032              // word-stride 516 = 4 mod 32: bank-free b-frags
#define SMEM_BYTES (16384 + 8 * VT_STRIDE * 2)   // 32896

__device__ __forceinline__ unsigned h2pk(float hi, float lo) {
    unsigned r; asm("cvt.rn.f16x2.f32 %0,%1,%2;" : "=r"(r) : "f"(hi), "f"(lo)); return r;
}
__device__ __forceinline__ unsigned ex2h2(unsigned x) {
    unsigned r; asm("ex2.approx.f16x2 %0,%1;" : "=r"(r) : "r"(x)); return r;
}
__device__ __forceinline__ unsigned hadd2(unsigned a, unsigned b) {
    unsigned r; asm("add.rn.f16x2 %0,%1,%2;" : "=r"(r) : "r"(a), "r"(b)); return r;
}
__device__ __forceinline__ float2 h2f2(unsigned v) {
    __half2 h = *(__half2*)&v;
    return __half22float2(h);
}
__device__ __forceinline__ void mma_16x8x8(float& c0, float& c1, float& c2, float& c3,
                                           unsigned a0, unsigned a1, unsigned b0) {
    asm("mma.sync.aligned.m16n8k8.row.col.f32.f16.f16.f32 "
        "{%0,%1,%2,%3},{%4,%5},{%6},{%0,%1,%2,%3};"
        : "+f"(c0), "+f"(c1), "+f"(c2), "+f"(c3)
        : "r"(a0), "r"(a1), "r"(b0));
}
__device__ __forceinline__ void mma_16x8x16(float& c0, float& c1, float& c2, float& c3,
                                            unsigned a0, unsigned a1, unsigned a2, unsigned a3,
                                            unsigned b0, unsigned b1) {
    asm("mma.sync.aligned.m16n8k16.row.col.f32.f16.f16.f32 "
        "{%0,%1,%2,%3},{%4,%5,%6,%7},{%8,%9},{%0,%1,%2,%3};"
        : "+f"(c0), "+f"(c1), "+f"(c2), "+f"(c3)
        : "r"(a0), "r"(a1), "r"(a2), "r"(a3), "r"(b0), "r"(b1));
}

// ---------------------------------------------------------------------------
// Fused qlayer + flash-attention via mma.sync, at the mma.sync tensor floor:
// per 32 keys: 4 QK k8 mmas + 2 PV k16 mmas (128 tensor-cyc) — no kl
// compensation, no ones-mma. Softmax weights via ex2.approx.f16x2; row-sums L
// via fp16x2 add tree -> f32 accum -> quad shuffle.
// Grid: 512 blocks = 64 heads x 8 row-tiles; 256 thr = 8 warps x 16 q-rows.
// ---------------------------------------------------------------------------
__global__ __launch_bounds__(256) void attn_kernel(const float* __restrict__ x,
                                                   const float* __restrict__ phi) {
    extern __shared__ char dynsmem[];
    __half*  kh = (__half*)(dynsmem + SM_KH);       // [j][8] row-major fp16
    __half*  vt = (__half*)(dynsmem + SM_VT);       // [d][VT_STRIDE] fp16
    const unsigned* khw = (const unsigned*)kh;      // half2 words: [j*4 + p]
    const unsigned* vtw = (const unsigned*)vt;      // [d*516 + j/2]

    const int bh = blockIdx.x >> 3;
    const int b = bh >> 3, h = bh & 7;
    const int tid = threadIdx.x;

    float ph0 = phi[0], ph1 = phi[1], ph2 = phi[2], ph3 = phi[3];
    float ph4 = phi[4], ph5 = phi[5], ph6 = phi[6], ph7 = phi[7];

    // ---- prologue: qlayer (prefix products of cos) -> kh (vec) and vt ----
    #pragma unroll
    for (int it = 0; it < 4; it++) {
        int s = tid + it * 256;
        const float4* xp = (const float4*)(x + ((size_t)((b << 10) + s) << 6) + (h << 3));
        float4 xa = xp[0];
        float4 xb = xp[1];
        float k0 = __cosf(xa.x + ph0);
        float c1 = __cosf(xa.y + ph1);
        float c2 = __cosf(xa.z + ph2);
        float c3 = __cosf(xa.w + ph3);
        float c4 = __cosf(xb.x + ph4);
        float c5 = __cosf(xb.y + ph5);
        float c6 = __cosf(xb.z + ph6);
        float c7 = __cosf(xb.w + ph7);
        float kv1 = k0 * c1;
        float kv2 = kv1 * c2;
        float kv3 = kv2 * c3;
        float kv4 = kv3 * c4;
        float kv5 = kv4 * c5;
        float kv6 = kv5 * c6;
        float kv7 = kv6 * c7;
        float t = c1 * c2;
        t *= c3; t *= c4; t *= c5; t *= c6; t *= c7;

        unsigned w0 = h2pk(kv1, t);
        unsigned w1 = h2pk(kv3, kv2);
        unsigned w2 = h2pk(kv5, kv4);
        unsigned w3 = h2pk(kv7, kv6);
        ((uint4*)kh)[s] = make_uint4(w0, w1, w2, w3);

        __half2 p0 = *(__half2*)&w0, p1 = *(__half2*)&w1;
        __half2 p2 = *(__half2*)&w2, p3 = *(__half2*)&w3;
        vt[0 * VT_STRIDE + s] = p0.x;
        vt[1 * VT_STRIDE + s] = p0.y;
        vt[2 * VT_STRIDE + s] = p1.x;
        vt[3 * VT_STRIDE + s] = p1.y;
        vt[4 * VT_STRIDE + s] = p2.x;
        vt[5 * VT_STRIDE + s] = p2.y;
        vt[6 * VT_STRIDE + s] = p3.x;
        vt[7 * VT_STRIDE + s] = p3.y;
    }
    __syncthreads();

    // ---- per-warp Q fragments: q = fp16(k * log2e/sqrt8) ----
    const int wid = tid >> 5, lane = tid & 31;
    const int r0 = ((blockIdx.x & 7) << 7) + (wid << 4);
    const int qr = lane >> 2, qm = lane & 3;
    const float SC = 0.35355339059327373f * 1.4426950408889634f;

    unsigned qh_a0, qh_a1;
    {
        unsigned w0 = khw[(r0 + qr) * 4 + qm];
        float2 f0 = h2f2(w0);
        qh_a0 = h2pk(f0.y * SC, f0.x * SC);
        unsigned w1 = khw[(r0 + qr + 8) * 4 + qm];
        float2 f1 = h2f2(w1);
        qh_a1 = h2pk(f1.y * SC, f1.x * SC);
    }

    float o0 = 0.f, o1 = 0.f, o2 = 0.f, o3 = 0.f;   // O accum (16x8)
    float l0 = 0.f, l1 = 0.f;                        // f32 row-sum partials

    const int vbase = (lane >> 2) * (VT_STRIDE / 2) + (lane & 3);

    for (int c = 0; c < SS; c += 32) {
        // ---- b-frag loads ----
        unsigned b0 = khw[(c +  0) * 4 + lane];
        unsigned b1 = khw[(c +  8) * 4 + lane];
        unsigned b2 = khw[(c + 16) * 4 + lane];
        unsigned b3 = khw[(c + 24) * 4 + lane];
        unsigned vb0 = vtw[vbase + (c >> 1)];
        unsigned vb1 = vtw[vbase + (c >> 1) + 4];
        unsigned vb2 = vtw[vbase + (c >> 1) + 8];
        unsigned vb3 = vtw[vbase + (c >> 1) + 12];

        // ---- 4 QK mmas (tensor floor) ----
        float s00=0.f,s01=0.f,s02=0.f,s03=0.f;
        float s10=0.f,s11=0.f,s12=0.f,s13=0.f;
        float s20=0.f,s21=0.f,s22=0.f,s23=0.f;
        float s30=0.f,s31=0.f,s32=0.f,s33=0.f;
        mma_16x8x8(s00,s01,s02,s03, qh_a0,qh_a1, b0);
        mma_16x8x8(s10,s11,s12,s13, qh_a0,qh_a1, b1);
        mma_16x8x8(s20,s21,s22,s23, qh_a0,qh_a1, b2);
        mma_16x8x8(s30,s31,s32,s33, qh_a0,qh_a1, b3);

        // ---- softmax weights: packed fp16 ex2 ----
        unsigned a00 = ex2h2(h2pk(s01, s00));   // row qr,   keys c..c+7
        unsigned a01 = ex2h2(h2pk(s03, s02));   // row qr+8
        unsigned a10 = ex2h2(h2pk(s11, s10));
        unsigned a11 = ex2h2(h2pk(s13, s12));
        unsigned a20 = ex2h2(h2pk(s21, s20));
        unsigned a21 = ex2h2(h2pk(s23, s22));
        unsigned a30 = ex2h2(h2pk(s31, s30));
        unsigned a31 = ex2h2(h2pk(s33, s32));

        // ---- L: fp16x2 add tree (sums <= 68, fp16-safe) -> f32 ----
        unsigned T0 = hadd2(hadd2(a00, a10), hadd2(a20, a30));
        unsigned T1 = hadd2(hadd2(a01, a11), hadd2(a21, a31));
        float2 f0 = h2f2(T0);
        float2 f1 = h2f2(T1);
        l0 += f0.x + f0.y;
        l1 += f1.x + f1.y;

        // ---- 2 PV mmas ----
        mma_16x8x16(o0, o1, o2, o3, a00, a01, a10, a11, vb0, vb1);
        mma_16x8x16(o0, o1, o2, o3, a20, a21, a30, a31, vb2, vb3);
    }

    // ---- complete row sums across the quad (cols live on 4 lanes) ----
    l0 += __shfl_xor_sync(0xffffffffu, l0, 1);
    l0 += __shfl_xor_sync(0xffffffffu, l0, 2);
    l1 += __shfl_xor_sync(0xffffffffu, l1, 1);
    l1 += __shfl_xor_sync(0xffffffffu, l1, 2);
    float inv0 = 1.f / l0;
    float inv1 = 1.f / l1;

    // ---- write O: rows r0+qr, r0+qr+8; dims 2*qm, 2*qm+1 ----
    {
        int s0 = r0 + qr;
        float2* p0 = (float2*)&g_ao[((((size_t)b << 10) + s0) << 6) + (h << 3) + (qm << 1)];
        *p0 = make_float2(o0 * inv0, o1 * inv0);
        int s1 = s0 + 8;
        float2* p1 = (float2*)&g_ao[((((size_t)b << 10) + s1) << 6) + (h << 3) + (qm << 1)];
        *p1 = make_float2(o2 * inv1, o3 * inv1);
    }
}

// ---------------------------------------------------------------------------
// Epilogue: out = ao @ W^T + b.  W rows in REGISTERS (lane owns column e);
// 256 blocks x 32 rows -> 2 blocks/SM, 4 warps/SMSP. 8 rows/thread as two
// 4-row ILP batches.
// ---------------------------------------------------------------------------
__global__ __launch_bounds__(256) void epilogue_kernel(const float* __restrict__ W,
                                                       const float* __restrict__ bias,
                                                       float* __restrict__ out) {
    __shared__ float ssin[32 * 64];      // 8 KB

    const int tid = threadIdx.x;
    const int row0 = blockIdx.x * 32;

    const float4* src = (const float4*)(g_ao + (size_t)row0 * 64);
    float4* dst = (float4*)ssin;
    #pragma unroll
    for (int i = 0; i < 2; i++)
        dst[tid + i * 256] = src[tid + i * 256];

    const int w = tid >> 5, lane = tid & 31;
    const int e = (w & 1) * 32 + lane;
    float wreg[64];
    const float4* wsrc = (const float4*)(W + e * 64);
    #pragma unroll
    for (int i = 0; i < 16; i++) {
        float4 v = wsrc[i];
        wreg[4 * i + 0] = v.x;
        wreg[4 * i + 1] = v.y;
        wreg[4 * i + 2] = v.z;
        wreg[4 * i + 3] = v.w;
    }
    const float be = bias[e];
    __syncthreads();

    const int rbase = (w >> 1) * 8;      // 8 rows per warp-pair group
    #pragma unroll
    for (int rr = 0; rr < 8; rr += 4) {
        const float4* s0 = (const float4*)&ssin[(rbase + rr + 0) * 64];
        const float4* s1 = (const float4*)&ssin[(rbase + rr + 1) * 64];
        const float4* s2 = (const float4*)&ssin[(rbase + rr + 2) * 64];
        const float4* s3 = (const float4*)&ssin[(rbase + rr + 3) * 64];
        float a0 = be, a1 = be, a2 = be, a3 = be;
        #pragma unroll
        for (int i = 0; i < 16; i++) {
            float4 v0 = s0[i], v1 = s1[i], v2 = s2[i], v3 = s3[i];
            a0 += v0.x * wreg[4*i+0]; a0 += v0.y * wreg[4*i+1];
            a0 += v0.z * wreg[4*i+2]; a0 += v0.w * wreg[4*i+3];
            a1 += v1.x * wreg[4*i+0]; a1 += v1.y * wreg[4*i+1];
            a1 += v1.z * wreg[4*i+2]; a1 += v1.w * wreg[4*i+3];
            a2 += v2.x * wreg[4*i+0]; a2 += v2.y * wreg[4*i+1];
            a2 += v2.z * wreg[4*i+2]; a2 += v2.w * wreg[4*i+3];
            a3 += v3.x * wreg[4*i+0]; a3 += v3.y * wreg[4*i+1];
            a3 += v3.z * wreg[4*i+2]; a3 += v3.w * wreg[4*i+3];
        }
        int r = row0 + rbase + rr;
        out[(r + 0) * 64 + e] = a0;
        out[(r + 1) * 64 + e] = a1;
        out[(r + 2) * 64 + e] = a2;
        out[(r + 3) * 64 + e] = a3;
    }
}

// ---------------------------------------------------------------------------
extern "C" void kernel_launch(void* const* d_in, const int* in_sizes, int n_in,
                              void* d_out, int out_size) {
    const float* x    = (const float*)d_in[0];
    const float* phi  = (const float*)d_in[1];
    const float* W    = (const float*)d_in[2];
    const float* bias = (const float*)d_in[3];
    float* out = (float*)d_out;

    cudaFuncSetAttribute(attn_kernel, cudaFuncAttributeMaxDynamicSharedMemorySize,
                         SMEM_BYTES);
    attn_kernel<<<BH * 8, 256, SMEM_BYTES>>>(x, phi);
    epilogue_kernel<<<(BB * SS) / 32, 256>>>(W, bias, out);
}